// round 12
// baseline (speedup 1.0000x reference)
#include <cuda_runtime.h>
#include <cuda_bf16.h>
#include <cstdint>
#include <math.h>

#define BB   64
#define SS   512
#define HID  1024
#define G4   4096
#define ROWS (BB*SS)
#define NCTA 128

// ---------------- device scratch ----------------
__device__ __nv_bfloat16 g_xh[ROWS*HID];
__device__ __nv_bfloat16 g_xl[ROWS*HID];
__device__ __nv_bfloat16 g_wih[(size_t)G4*HID];
__device__ __nv_bfloat16 g_wil[(size_t)G4*HID];
__device__ __nv_bfloat16 g_whh[(size_t)G4*HID];
__device__ __nv_bfloat16 g_whl[(size_t)G4*HID];
__device__ float g_bias[G4];
__device__ float g_xproj[(size_t)SS*BB*G4];
__device__ __nv_bfloat16 g_hh[2][BB*HID];
__device__ __nv_bfloat16 g_hl[2][BB*HID];
__device__ int g_flag[NCTA];

// ---------------- helpers ----------------
__device__ __forceinline__ uint32_t cvta_s(const void* p){
    return (uint32_t)__cvta_generic_to_shared(p);
}
__device__ __forceinline__ uint32_t lds32(uint32_t a){
    uint32_t v; asm volatile("ld.shared.b32 %0,[%1];" : "=r"(v) : "r"(a)); return v;
}
__device__ __forceinline__ void cpa16(uint32_t s, const void* g){
    asm volatile("cp.async.cg.shared.global [%0],[%1],16;" :: "r"(s), "l"(g));
}
#define CP_COMMIT() asm volatile("cp.async.commit_group;")
#define CP_WAIT(N)  asm volatile("cp.async.wait_group %0;" :: "n"(N))

#define MMA_BF16(d, a, b) \
    asm volatile("mma.sync.aligned.m16n8k16.row.col.f32.bf16.bf16.f32 " \
                 "{%0,%1,%2,%3},{%4,%5,%6,%7},{%8,%9},{%0,%1,%2,%3};" \
                 : "+f"(d[0]), "+f"(d[1]), "+f"(d[2]), "+f"(d[3]) \
                 : "r"(a[0]), "r"(a[1]), "r"(a[2]), "r"(a[3]), "r"(b[0]), "r"(b[1]))

#define LDSM4(r, a) \
    asm volatile("ldmatrix.sync.aligned.m8n8.x4.shared.b16 {%0,%1,%2,%3}, [%4];" \
                 : "=r"((r)[0]), "=r"((r)[1]), "=r"((r)[2]), "=r"((r)[3]) : "r"(a))

__device__ __forceinline__ float sigm(float x){ return 1.f/(1.f + __expf(-x)); }

// ---------------- prep ----------------
__global__ void k_split_x(const float* __restrict__ x){
    int i = blockIdx.x*blockDim.x + threadIdx.x;
    int stride = gridDim.x*blockDim.x;
    for (; i < ROWS*HID; i += stride){
        float v = x[i];
        __nv_bfloat16 h = __float2bfloat16(v);
        g_xh[i] = h;
        g_xl[i] = __float2bfloat16(v - __bfloat162float(h));
    }
}

// transposed + gate-interleaved weights (col = 4*j + gate), hi/lo split
__global__ void k_prep_w(const float* Wii, const float* Wfi, const float* Wgi, const float* Woi,
                         const float* Wih, const float* Wfh, const float* Wgh, const float* Woh,
                         const float* bii, const float* bih, const float* bfi, const float* bfh,
                         const float* bgi, const float* bgh, const float* boi, const float* boh){
    size_t idx = (size_t)blockIdx.x*256 + threadIdx.x;
    if (idx >= (size_t)G4*HID) return;
    int c = (int)(idx >> 10), k = (int)(idx & 1023);
    int j = c >> 2, gg = c & 3;
    const float* wi = (gg==0)?Wii:(gg==1)?Wfi:(gg==2)?Wgi:Woi;
    const float* wh = (gg==0)?Wih:(gg==1)?Wfh:(gg==2)?Wgh:Woh;
    float vi = wi[(size_t)k*HID + j];
    float vh = wh[(size_t)k*HID + j];
    __nv_bfloat16 h1 = __float2bfloat16(vi);
    g_wih[idx] = h1; g_wil[idx] = __float2bfloat16(vi - __bfloat162float(h1));
    __nv_bfloat16 h2 = __float2bfloat16(vh);
    g_whh[idx] = h2; g_whl[idx] = __float2bfloat16(vh - __bfloat162float(h2));
    if (idx < G4){
        int jj = (int)(idx >> 2); int g2 = (int)(idx & 3);
        const float* b1 = (g2==0)?bii:(g2==1)?bfi:(g2==2)?bgi:boi;
        const float* b2 = (g2==0)?bih:(g2==1)?bfh:(g2==2)?bgh:boh;
        g_bias[idx] = b1[jj] + b2[jj];
    }
}

__global__ void k_init(){
    int i = blockIdx.x*256 + threadIdx.x;
    __nv_bfloat16 z = __float2bfloat16(0.f);
    g_hh[0][i] = z; g_hh[1][i] = z;
    g_hl[0][i] = z; g_hl[1][i] = z;
    if (i < NCTA) g_flag[i] = 0;
}

// ---------------- xproj GEMM [32768,1024]x[1024,4096], 3-term, tile 128x128 ----
#define XP_STAGE 24576
#define RB 48

__global__ void __launch_bounds__(256) k_xproj(){
    extern __shared__ __align__(16) char smem_raw[];
    const uint32_t sbase = cvta_s(smem_raw);
    int tid = threadIdx.x;
    int lane = tid & 31, warp = tid >> 5;
    int g = lane >> 2, tq = lane & 3;
    int wm = warp >> 2, wn = warp & 3;
    int m0 = blockIdx.y * 128, n0 = blockIdx.x * 128;

    auto stage_load = [&](int kt, int s){
        int arr = tid >> 7, rem = tid & 127;
        int chunk = rem & 1, rc = rem >> 1;
        const __nv_bfloat16* gA = arr ? g_xl : g_xh;
        const __nv_bfloat16* gB = arr ? g_wil : g_wih;
        uint32_t aA = sbase + s*XP_STAGE + arr*6144;
        uint32_t aB = sbase + s*XP_STAGE + 12288 + arr*6144;
        #pragma unroll
        for (int i = 0; i < 2; i++){
            int row = rc + i*64;
            cpa16(aA + row*RB + chunk*16, gA + (size_t)(m0+row)*HID + kt*16 + chunk*8);
            cpa16(aB + row*RB + chunk*16, gB + (size_t)(n0+row)*HID + kt*16 + chunk*8);
        }
        CP_COMMIT();
    };

    stage_load(0, 0);
    stage_load(1, 1);

    float acc[4][4][4];
    #pragma unroll
    for (int ma = 0; ma < 4; ma++)
        #pragma unroll
        for (int na = 0; na < 4; na++){
            int c = n0 + wn*32 + na*8 + 2*tq;
            float b0 = g_bias[c], b1 = g_bias[c+1];
            acc[ma][na][0] = b0; acc[ma][na][1] = b1;
            acc[ma][na][2] = b0; acc[ma][na][3] = b1;
        }

    for (int kt = 0; kt < 64; kt++){
        CP_WAIT(1);
        __syncthreads();
        if (kt + 2 < 64) stage_load(kt + 2, (kt + 2) % 3);
        else CP_COMMIT();

        uint32_t st = sbase + (kt % 3)*XP_STAGE;
        uint32_t Ah = st, Al = st + 6144, Bh = st + 12288, Bl = st + 18432;
        uint32_t ah[4][4], al[4][4], bh[4][2], bl[4][2];
        #pragma unroll
        for (int ma = 0; ma < 4; ma++){
            int r = wm*64 + ma*16 + g;
            uint32_t o0 = r*RB + tq*4, o1 = (r+8)*RB + tq*4;
            ah[ma][0] = lds32(Ah + o0);      ah[ma][1] = lds32(Ah + o1);
            ah[ma][2] = lds32(Ah + o0 + 16); ah[ma][3] = lds32(Ah + o1 + 16);
            al[ma][0] = lds32(Al + o0);      al[ma][1] = lds32(Al + o1);
            al[ma][2] = lds32(Al + o0 + 16); al[ma][3] = lds32(Al + o1 + 16);
        }
        #pragma unroll
        for (int na = 0; na < 4; na++){
            int cb = wn*32 + na*8 + g;
            uint32_t o = cb*RB + tq*4;
            bh[na][0] = lds32(Bh + o); bh[na][1] = lds32(Bh + o + 16);
            bl[na][0] = lds32(Bl + o); bl[na][1] = lds32(Bl + o + 16);
        }
        #pragma unroll
        for (int ma = 0; ma < 4; ma++)
            #pragma unroll
            for (int na = 0; na < 4; na++){
                MMA_BF16(acc[ma][na], ah[ma], bh[na]);
                MMA_BF16(acc[ma][na], ah[ma], bl[na]);
                MMA_BF16(acc[ma][na], al[ma], bh[na]);
            }
    }

    CP_WAIT(0);
    __syncthreads();
    float* sOut = (float*)smem_raw;  // 128 x 132
    #pragma unroll
    for (int ma = 0; ma < 4; ma++)
        #pragma unroll
        for (int na = 0; na < 4; na++){
            int r = wm*64 + ma*16 + g;
            int c = wn*32 + na*8 + 2*tq;
            sOut[r*132 + c]       = acc[ma][na][0];
            sOut[r*132 + c + 1]   = acc[ma][na][1];
            sOut[(r+8)*132 + c]   = acc[ma][na][2];
            sOut[(r+8)*132 + c+1] = acc[ma][na][3];
        }
    __syncthreads();
    #pragma unroll
    for (int it = 0; it < 16; it++){
        int r2 = (tid >> 5) + it*8;
        int rg = m0 + r2;
        int b = rg >> 9, s = rg & 511;
        float4 v = *(float4*)(sOut + r2*132 + lane*4);
        *(float4*)(g_xproj + ((size_t)(s*64 + b))*G4 + n0 + lane*4) = v;
    }
}

// ---------------- persistent HMMA+ldmatrix recurrence ----------------
// SMEM map (bytes):
//   [0, 131072)        B resident: hi [0,65536) lo [65536,131072).
//                      Per array: 16 chunks x 4096 B; chunk = 32 rows x 128 B,
//                      atoms of 8 rows: (r>>3)*1024 + swz((r&7)*128 + cbyte)
//   [131072, 196608)   A stages: 4 x 16384. Stage: 128 rows (64 h-hi, 64 h-lo)
//                      x 128 B, same atom/swizzle scheme
//   [196608, 205824)   sG gate buffer: 64 x 36 floats
#define TC_B    0u
#define TC_BLO  65536u
#define TC_A    131072u
#define TC_SG   196608u
#define TC_SMEM 205824

__global__ void __launch_bounds__(256, 1) k_recur(float* __restrict__ out){
    extern __shared__ __align__(16) char smem_raw[];
    const uint32_t sbase = cvta_s(smem_raw);
    float* sG = (float*)(smem_raw + TC_SG);
    int tid = threadIdx.x;
    int lane = tid & 31, warp = tid >> 5;
    int g = lane >> 2, tq = lane & 3;
    int wm = warp & 3, wn = warp >> 2;       // 4 m-tiles x 2 n-halves
    int n0 = blockIdx.x * 32;

    // ---- resident Wh slice load (once) ----
    for (int i = tid; i < 8192; i += 256){
        int arr = i >> 12, j = i & 4095;
        int c = j >> 8, r = (j >> 3) & 31, seg = j & 7;
        uint32_t dst = sbase + TC_B + (uint32_t)arr*TC_BLO + (uint32_t)c*4096u
                     + (uint32_t)(r >> 3)*1024u + (uint32_t)(r & 7)*128u
                     + ((uint32_t)(seg*16) ^ ((uint32_t)(r & 7) << 4));
        const __nv_bfloat16* src = (arr ? g_whl : g_whh)
            + (size_t)(n0 + r)*HID + c*64 + seg*8;
        cpa16(dst, src);
    }
    CP_COMMIT();

    // per-lane ldmatrix address constants
    int R0 = wm*16 + (lane & 15);            // A hi row
    uint32_t PaH = (uint32_t)(R0 >> 3)*1024u + (uint32_t)(R0 & 7)*128u;
    int RL = R0 + 64;                        // A lo row
    uint32_t PaL = (uint32_t)(RL >> 3)*1024u + (uint32_t)(RL & 7)*128u;
    uint32_t Qa  = (uint32_t)(R0 & 7) << 4;
    uint32_t kh16 = (uint32_t)(lane >> 4)*16u;
    int rB = (lane & 7);
    uint32_t Qb = (uint32_t)rB << 4;
    uint32_t qb16 = (uint32_t)(lane >> 3)*16u;
    uint32_t PbBase[2];
    #pragma unroll
    for (int nf = 0; nf < 2; nf++){
        int rn = wn*16 + nf*8 + rB;          // B row (n)
        PbBase[nf] = (uint32_t)(rn >> 3)*1024u + (uint32_t)(rn & 7)*128u;
    }

    float cst[2] = {0.f, 0.f};

    for (int t = 0; t < SS; t++){
        const __nv_bfloat16* hinH = g_hh[t & 1];
        const __nv_bfloat16* hinL = g_hl[t & 1];

        auto load_chunk = [&](int c){
            int half = tid >> 7, rem = tid & 127;
            int row = rem >> 1, sb = (rem & 1)*4;
            int R = half*64 + row;
            uint32_t dstb = sbase + TC_A + (uint32_t)(c & 3)*16384u
                          + (uint32_t)(R >> 3)*1024u + (uint32_t)(R & 7)*128u;
            const __nv_bfloat16* src = (half ? hinL : hinH)
                + (size_t)row*HID + c*64 + sb*8;
            #pragma unroll
            for (int i = 0; i < 4; i++){
                uint32_t cbyte = (uint32_t)((sb + i)*16);
                cpa16(dstb + (cbyte ^ ((uint32_t)(R & 7) << 4)), src + i*8);
            }
            CP_COMMIT();
        };

        load_chunk(0); load_chunk(1); load_chunk(2);

        float acc[2][4];
        {
            const float* xp  = g_xproj + ((size_t)t*BB + wm*16 + g)*G4 + n0;
            const float* xp2 = xp + 8*G4;
            #pragma unroll
            for (int nf = 0; nf < 2; nf++){
                int cc = wn*16 + nf*8 + 2*tq;
                acc[nf][0] = xp[cc];  acc[nf][1] = xp[cc+1];
                acc[nf][2] = xp2[cc]; acc[nf][3] = xp2[cc+1];
            }
        }

        for (int c = 0; c < 16; c++){
            CP_WAIT(2);
            __syncthreads();
            if (c + 3 < 16) load_chunk(c + 3);
            else CP_COMMIT();

            uint32_t Ab = sbase + TC_A + (uint32_t)(c & 3)*16384u;
            uint32_t Bb = sbase + TC_B + (uint32_t)c*4096u;
            #pragma unroll
            for (int pr = 0; pr < 2; pr++){
                uint32_t bh[2][4], bl[2][4];
                #pragma unroll
                for (int nf = 0; nf < 2; nf++){
                    uint32_t cb = ((uint32_t)(pr*64) + qb16) ^ Qb;
                    LDSM4(bh[nf], Bb + PbBase[nf] + cb);
                    LDSM4(bl[nf], Bb + TC_BLO + PbBase[nf] + cb);
                }
                #pragma unroll
                for (int k2 = 0; k2 < 2; k2++){
                    uint32_t cbA = ((uint32_t)(pr*64 + k2*32) + kh16) ^ Qa;
                    uint32_t ah[4], al[4];
                    LDSM4(ah, Ab + PaH + cbA);
                    LDSM4(al, Ab + PaL + cbA);
                    #pragma unroll
                    for (int nf = 0; nf < 2; nf++){
                        uint32_t* bp = bh[nf] + k2*2;
                        uint32_t* lp = bl[nf] + k2*2;
                        MMA_BF16(acc[nf], ah, bp);
                        MMA_BF16(acc[nf], ah, lp);
                        MMA_BF16(acc[nf], al, bp);
                    }
                }
            }
        }

        // ---- epilogue: dump gates, cell update ----
        #pragma unroll
        for (int nf = 0; nf < 2; nf++){
            int r = wm*16 + g;
            int cc = wn*16 + nf*8 + 2*tq;
            sG[r*36 + cc]       = acc[nf][0];
            sG[r*36 + cc + 1]   = acc[nf][1];
            sG[(r+8)*36 + cc]   = acc[nf][2];
            sG[(r+8)*36 + cc+1] = acc[nf][3];
        }
        __syncthreads();

        bool last = (t == SS - 1);
        __nv_bfloat16* houtH = g_hh[(t + 1) & 1];
        __nv_bfloat16* houtL = g_hl[(t + 1) & 1];
        #pragma unroll
        for (int p = 0; p < 2; p++){
            int pair = p*256 + tid;            // 0..511
            int b = pair >> 3, jl = pair & 7;
            float4 gt = *(float4*)(sG + b*36 + jl*4);
            float iv = sigm(gt.x);
            float fv = sigm(gt.y);
            float gv = tanhf(gt.z);
            float ov = sigm(gt.w);
            float cn = fv*cst[p] + iv*gv;
            cst[p] = cn;
            float h = ov*tanhf(cn);
            int ci = b*HID + (n0 >> 2) + jl;
            __nv_bfloat16 hh = __float2bfloat16(h);
            float hlf = h - __bfloat162float(hh);
            __nv_bfloat16 hl = __float2bfloat16(hlf);
            asm volatile("st.global.cg.u16 [%0], %1;" :: "l"(houtH + ci),
                         "h"(*(const unsigned short*)&hh));
            asm volatile("st.global.cg.u16 [%0], %1;" :: "l"(houtL + ci),
                         "h"(*(const unsigned short*)&hl));
            if (last){ out[ci] = h; out[BB*HID + ci] = cn; }
        }
        __syncthreads();

        // ---- distributed grid barrier ----
        if (tid == 0){
            __threadfence();
            asm volatile("st.global.release.gpu.s32 [%0], %1;"
                         :: "l"(g_flag + blockIdx.x), "r"(t + 1) : "memory");
        }
        if (tid < NCTA){
            int v;
            do {
                asm volatile("ld.global.acquire.gpu.s32 %0, [%1];"
                             : "=r"(v) : "l"(g_flag + tid));
            } while (v < t + 1);
        }
        __syncthreads();
    }
}

// ---------------- launch ----------------
extern "C" void kernel_launch(void* const* d_in, const int* in_sizes, int n_in,
                              void* d_out, int out_size){
    // dict order: x, Wii,Wfi,Wgi,Woi, Wih,Wfh,Wgh,Woh, bii,bih,bfi,bfh,bgi,bgh,boi,boh
    const float* x = nullptr;
    const float* w[8] = {nullptr}; const float* bp[8] = {nullptr};
    int nw = 0, nb = 0;
    for (int i = 0; i < n_in; i++){
        if (in_sizes[i] == ROWS*HID)      x = (const float*)d_in[i];
        else if (in_sizes[i] == HID*HID){ if (nw < 8) w[nw++] = (const float*)d_in[i]; }
        else if (in_sizes[i] == HID){     if (nb < 8) bp[nb++] = (const float*)d_in[i]; }
    }
    float* out = (float*)d_out;

    cudaFuncSetAttribute(k_xproj, cudaFuncAttributeMaxDynamicSharedMemorySize, 3*XP_STAGE);
    cudaFuncSetAttribute(k_recur, cudaFuncAttributeMaxDynamicSharedMemorySize, TC_SMEM);

    k_split_x<<<2048, 256>>>(x);
    k_prep_w<<<16384, 256>>>(w[0], w[1], w[2], w[3], w[4], w[5], w[6], w[7],
                             bp[0], bp[1], bp[2], bp[3], bp[4], bp[5], bp[6], bp[7]);
    k_init<<<256, 256>>>();
    dim3 gx(32, 256);
    k_xproj<<<gx, 256, 3*XP_STAGE>>>();
    k_recur<<<NCTA, 256, TC_SMEM>>>(out);
}